// round 16
// baseline (speedup 1.0000x reference)
#include <cuda_runtime.h>
#include <cuda_fp16.h>
#include <math.h>
#include <stdint.h>
#include <float.h>

#define PLEN 14
#define BATCH 4096
#define N_NODES (BATCH * PLEN)   // 57344
#define TW2 (2 * N_NODES)        // both towers
#define BN_EPS 1e-5f

// Output layout: concat of (sim[B], c1[B,800], c2[B,800], e1[B,10], e2[B,10], d1[B,800])
#define O_SIM 0
#define O_C1  4096
#define O_C2  (4096 + 3276800)
#define O_E1  (4096 + 2*3276800)
#define O_E2  (O_E1 + 40960)
#define O_D1  (O_E2 + 40960)

// ---------------- scratch (device globals; no allocation) ----------------
__device__ float g_hA[(size_t)TW2 * 128];
__device__ float g_hB[(size_t)TW2 * 128];
__device__ float g_sum[2][5][1024];
__device__ float g_sq [2][5][1024];
__device__ float g_e  [2][BATCH * 10];
__device__ __align__(16) __half g_A5[(size_t)TW2 * 128];     // fp16 A for layer5
__device__ __align__(16) __half g_W5T[1024 * 128];           // W5^T fp16: [n][k]
// per-(molecule,col) pooling partials; molecule id is GLOBAL (0..2*BATCH-1)
__device__ float g_mxH[2 * BATCH * 1024], g_mnH[2 * BATCH * 1024];
__device__ float g_mxT[2 * BATCH * 1024], g_mnT[2 * BATCH * 1024];

// ---------------- setup: W5 transpose->fp16 + zero BN stat accumulators ----------------
__global__ void setup_kernel(const float* __restrict__ W5) {
    int i = blockIdx.x * 256 + threadIdx.x;   // 0..131071
    if (i < 2 * 5 * 1024) {
        (&g_sum[0][0][0])[i] = 0.0f;
        (&g_sq [0][0][0])[i] = 0.0f;
    }
    int k = i >> 10, n = i & 1023;            // 128*1024 total
    g_W5T[n * 128 + k] = __float2half(W5[i]);
}

// ---------------- layer 1 (both towers), stride-64 output ----------------
__global__ void __launch_bounds__(256) layer1_kernel(const float* __restrict__ x1,
                                                     const float* __restrict__ x2,
                                                     const float* __restrict__ W1,
                                                     const float* __restrict__ b1) {
    __shared__ float xg[64][3];
    int tid = threadIdx.x;
    int rowBase = blockIdx.x * 64;
    int tw = rowBase >= N_NODES;
    const float* x = tw ? x2 : x1;
    int locBase = rowBase - tw * N_NODES;
    if (tid < 192) {
        int i = tid / 3, k = tid % 3;
        int nl = locBase + i, b = nl / PLEN, p = nl % PLEN;
        const float* xb = x + (size_t)b * 3 * PLEN + k * PLEN;
        float v = 0.0f;
        if (p > 0)        v += xb[p - 1];
        if (p < PLEN - 1) v += xb[p + 1];
        xg[i][k] = v;
    }
    __syncthreads();
    int c = tid & 63, rg = tid >> 6;
    float w0 = W1[c], w1 = W1[64 + c], w2 = W1[128 + c], bb = b1[c];
    float s1 = 0.0f, s2 = 0.0f;
    for (int ii = 0; ii < 16; ++ii) {
        int i = rg * 16 + ii;
        float v = fmaf(xg[i][0], w0, fmaf(xg[i][1], w1, fmaf(xg[i][2], w2, bb)));
        g_hA[(size_t)(rowBase + i) * 64 + c] = v;
        s1 += v; s2 = fmaf(v, v, s2);
    }
    atomicAdd(&g_sum[tw][0][c], s1);
    atomicAdd(&g_sq [tw][0][c], s2);
}

// ---------------- fp32 GCN GEMM (layers 2-4), M=128 tile, in-block BN affine ----------------
template<int K, int NT>
__global__ void __launch_bounds__(256)
gcn_gemm(const float* __restrict__ W, const float* __restrict__ bias,
         int srcBuf, int dstBuf,
         const float* __restrict__ gammaP, const float* __restrict__ betaP,
         int statPrev, int statIdx, int DOUT) {
    constexpr int M = 128, TN = NT / 16, K4 = K / 4, NT4 = NT / 4, MP = M + 4;
    extern __shared__ float sm[];
    float* As = sm;
    float* Bs = As + K * MP;
    float* sA = Bs + K * NT;
    float* sD = sA + K;

    const float* prev = srcBuf ? g_hB : g_hA;
    float* out = dstBuf ? g_hB : g_hA;

    int tid = threadIdx.x, tx = tid & 15, ty = tid >> 4;
    int rowBase = blockIdx.x * M, colBase = blockIdx.y * NT;
    int tw = rowBase >= N_NODES;

    if (tid < K) {
        const float invN = 1.0f / (float)N_NODES;
        float mu  = g_sum[tw][statPrev][tid] * invN;
        float var = g_sq[tw][statPrev][tid] * invN - mu * mu;
        float s = gammaP[tid] * rsqrtf(var + BN_EPS);
        sA[tid] = s; sD[tid] = betaP[tid] - mu * s;
    }
    for (int s = tid; s < K * NT4; s += 256) {
        int k = s / NT4, j = (s - k * NT4) * 4;
        float4 w = *reinterpret_cast<const float4*>(W + (size_t)k * DOUT + colBase + j);
        *reinterpret_cast<float4*>(&Bs[k * NT + j]) = w;
    }
    __syncthreads();
    for (int s = tid; s < M * K4; s += 256) {
        int i = s / K4, kq = (s - i * K4) * 4;
        int n = rowBase + i, p = n % PLEN;
        float v0 = 0.f, v1 = 0.f, v2 = 0.f, v3 = 0.f;
        float a0 = sA[kq], a1 = sA[kq + 1], a2 = sA[kq + 2], a3 = sA[kq + 3];
        float d0 = sD[kq], d1 = sD[kq + 1], d2 = sD[kq + 2], d3 = sD[kq + 3];
        if (p > 0) {
            float4 L = *reinterpret_cast<const float4*>(prev + (size_t)(n - 1) * K + kq);
            v0 += fmaxf(fmaf(a0, L.x, d0), 0.f);
            v1 += fmaxf(fmaf(a1, L.y, d1), 0.f);
            v2 += fmaxf(fmaf(a2, L.z, d2), 0.f);
            v3 += fmaxf(fmaf(a3, L.w, d3), 0.f);
        }
        if (p < PLEN - 1) {
            float4 R = *reinterpret_cast<const float4*>(prev + (size_t)(n + 1) * K + kq);
            v0 += fmaxf(fmaf(a0, R.x, d0), 0.f);
            v1 += fmaxf(fmaf(a1, R.y, d1), 0.f);
            v2 += fmaxf(fmaf(a2, R.z, d2), 0.f);
            v3 += fmaxf(fmaf(a3, R.w, d3), 0.f);
        }
        As[(kq + 0) * MP + i] = v0;
        As[(kq + 1) * MP + i] = v1;
        As[(kq + 2) * MP + i] = v2;
        As[(kq + 3) * MP + i] = v3;
    }
    __syncthreads();

    float acc[8][TN];
#pragma unroll
    for (int r = 0; r < 8; ++r)
#pragma unroll
        for (int j = 0; j < TN; ++j) acc[r][j] = 0.0f;

    int r0 = ty * 8, c0 = tx * TN;
#pragma unroll 4
    for (int k = 0; k < K; ++k) {
        float4 a4a = *reinterpret_cast<const float4*>(&As[k * MP + r0]);
        float4 a4b = *reinterpret_cast<const float4*>(&As[k * MP + r0 + 4]);
        float ar[8] = {a4a.x, a4a.y, a4a.z, a4a.w, a4b.x, a4b.y, a4b.z, a4b.w};
        float br[TN];
#pragma unroll
        for (int j = 0; j < TN; j += 4) {
            float4 b4 = *reinterpret_cast<const float4*>(&Bs[k * NT + c0 + j]);
            br[j] = b4.x; br[j + 1] = b4.y; br[j + 2] = b4.z; br[j + 3] = b4.w;
        }
#pragma unroll
        for (int r = 0; r < 8; ++r)
#pragma unroll
            for (int j = 0; j < TN; ++j)
                acc[r][j] = fmaf(ar[r], br[j], acc[r][j]);
    }
    __syncthreads();

    float bl[TN];
#pragma unroll
    for (int j = 0; j < TN; ++j) bl[j] = bias[colBase + c0 + j];

    float s1[TN], s2[TN];
#pragma unroll
    for (int j = 0; j < TN; ++j) { s1[j] = 0.f; s2[j] = 0.f; }

#pragma unroll
    for (int r = 0; r < 8; ++r) {
        float vrow[TN];
#pragma unroll
        for (int j = 0; j < TN; ++j) {
            float v = acc[r][j] + bl[j];
            vrow[j] = v; s1[j] += v; s2[j] = fmaf(v, v, s2[j]);
        }
        float* op = out + (size_t)(rowBase + r0 + r) * DOUT + colBase + c0;
#pragma unroll
        for (int j = 0; j < TN; j += 4) {
            float4 o = make_float4(vrow[j], vrow[j + 1], vrow[j + 2], vrow[j + 3]);
            *reinterpret_cast<float4*>(op + j) = o;
        }
    }
    float* red = As;
#pragma unroll
    for (int j = 0; j < TN; ++j) {
        red[ty * NT + c0 + j] = s1[j];
        red[16 * NT + ty * NT + c0 + j] = s2[j];
    }
    __syncthreads();
    if (tid < NT) {
        float t1 = 0.f, t2 = 0.f;
        for (int y = 0; y < 16; ++y) {
            t1 += red[y * NT + tid];
            t2 += red[16 * NT + y * NT + tid];
        }
        atomicAdd(&g_sum[tw][statIdx][colBase + tid], t1);
        atomicAdd(&g_sq [tw][statIdx][colBase + tid], t2);
    }
}

// ================= layer-5 tensor-core path (single-term fp16) =================

// A' = chain-agg(relu(BN4(g_hB))) -> fp16, affine computed per-block, both towers
__global__ void __launch_bounds__(256) prep_A5_kernel(const float* __restrict__ gamma,
                                                      const float* __restrict__ beta) {
    __shared__ float sa[128], sd[128];
    int tid = threadIdx.x;
    int rowCta = blockIdx.x * 128;
    int tw = rowCta >= N_NODES;
    if (tid < 128) {
        const float invN = 1.0f / (float)N_NODES;
        float mu  = g_sum[tw][3][tid] * invN;
        float var = g_sq[tw][3][tid] * invN - mu * mu;
        float s = gamma[tid] * rsqrtf(var + BN_EPS);
        sa[tid] = s; sd[tid] = beta[tid] - mu * s;
    }
    __syncthreads();
    for (int u = tid; u < 128 * 32; u += 256) {
        int i = u >> 5, kq = (u & 31) * 4;
        int n = rowCta + i, p = n % PLEN;
        float4 a = *reinterpret_cast<const float4*>(sa + kq);
        float4 d = *reinterpret_cast<const float4*>(sd + kq);
        float v0 = 0.f, v1 = 0.f, v2 = 0.f, v3 = 0.f;
        if (p > 0) {
            float4 L = *reinterpret_cast<const float4*>(g_hB + (size_t)(n - 1) * 128 + kq);
            v0 += fmaxf(fmaf(a.x, L.x, d.x), 0.f);
            v1 += fmaxf(fmaf(a.y, L.y, d.y), 0.f);
            v2 += fmaxf(fmaf(a.z, L.z, d.z), 0.f);
            v3 += fmaxf(fmaf(a.w, L.w, d.w), 0.f);
        }
        if (p < PLEN - 1) {
            float4 R = *reinterpret_cast<const float4*>(g_hB + (size_t)(n + 1) * 128 + kq);
            v0 += fmaxf(fmaf(a.x, R.x, d.x), 0.f);
            v1 += fmaxf(fmaf(a.y, R.y, d.y), 0.f);
            v2 += fmaxf(fmaf(a.z, R.z, d.z), 0.f);
            v3 += fmaxf(fmaf(a.w, R.w, d.w), 0.f);
        }
        size_t o = (size_t)n * 128 + kq;
        __half2* ph = reinterpret_cast<__half2*>(g_A5 + o);
        ph[0] = __halves2half2(__float2half(v0), __float2half(v1));
        ph[1] = __halves2half2(__float2half(v2), __float2half(v3));
    }
}

// smem layout (byte offsets); rows padded to 272B for conflict-free ldmatrix
// A: 64 rows fp16, B: 128 rows fp16, staging [64][132] fp32, bias. 2 CTAs/SM.
#define L5_STRIDE 272
#define SM_A    0
#define SM_BH   17408
#define SM_STAG 52224
#define SM_BIAS 86016
#define SM_TOT  86528

__device__ __forceinline__ uint32_t smem_u32(const void* p) {
    uint32_t a;
    asm("{ .reg .u64 t; cvta.to.shared.u64 t, %1; cvt.u32.u64 %0, t; }" : "=r"(a) : "l"(p));
    return a;
}
__device__ __forceinline__ void ldm4(uint32_t* r, uint32_t addr) {
    asm volatile("ldmatrix.sync.aligned.m8n8.x4.shared.b16 {%0,%1,%2,%3}, [%4];"
                 : "=r"(r[0]), "=r"(r[1]), "=r"(r[2]), "=r"(r[3]) : "r"(addr));
}
__device__ __forceinline__ void mma_f16(float* c, const uint32_t* a,
                                        uint32_t b0, uint32_t b1) {
    asm volatile(
        "mma.sync.aligned.m16n8k16.row.col.f32.f16.f16.f32 "
        "{%0,%1,%2,%3}, {%4,%5,%6,%7}, {%8,%9}, {%0,%1,%2,%3};"
        : "+f"(c[0]), "+f"(c[1]), "+f"(c[2]), "+f"(c[3])
        : "r"(a[0]), "r"(a[1]), "r"(a[2]), "r"(a[3]), "r"(b0), "r"(b1));
}

// grid: (8 col-blocks of 128, 224 row-groups of 512). Each CTA: B resident,
// loops 8 subtiles of 64 rows. 2 CTAs/SM.
__global__ void __launch_bounds__(256, 2)
layer5_mma(const float* __restrict__ bias) {
    extern __shared__ char sm5[];
    int tid = threadIdx.x, wid = tid >> 5, lane = tid & 31;
    int colBase = blockIdx.x * 128;
    int rowCta0 = blockIdx.y * 512;
    int tw = rowCta0 >= N_NODES;
    float* sbias = reinterpret_cast<float*>(sm5 + SM_BIAS);
    if (tid < 128) sbias[tid] = bias[colBase + tid];

    // B tile once per CTA: 128 n-rows x 128 k fp16
    {
        const uint4* bp = reinterpret_cast<const uint4*>(g_W5T) + (size_t)colBase * 16;
#pragma unroll
        for (int t = 0; t < 8; ++t) {
            int s = tid + t * 256;
            int row = s >> 4, c = s & 15;
            *reinterpret_cast<uint4*>(sm5 + SM_BH + row * L5_STRIDE + c * 16) = bp[s];
        }
    }

    int wm = wid >> 2, wn = wid & 3;
    int m0 = wm * 32, n0 = wn * 32;
    int quad = lane >> 3, r8 = lane & 7;
    uint32_t base = smem_u32(sm5);
    uint32_t aBase = base + SM_A + (uint32_t)((m0 + (quad & 1) * 8 + r8) * L5_STRIDE + (quad >> 1) * 16);
    uint32_t bBase = base + SM_BH + (uint32_t)((n0 + (quad >> 1) * 8 + r8) * L5_STRIDE + (quad & 1) * 16);

    float s1[4][2], s2[4][2];
#pragma unroll
    for (int nf = 0; nf < 4; ++nf) { s1[nf][0] = s1[nf][1] = 0.f; s2[nf][0] = s2[nf][1] = 0.f; }

    float* stag = reinterpret_cast<float*>(sm5 + SM_STAG);   // [64][132]

#pragma unroll 1
    for (int it = 0; it < 8; ++it) {
        int rowCta = rowCta0 + it * 64;
        __syncthreads();   // prev iter fully done before A overwrite
        {
            const uint4* ap = reinterpret_cast<const uint4*>(g_A5) + (size_t)rowCta * 16;
#pragma unroll
            for (int t = 0; t < 4; ++t) {
                int s = tid + t * 256;
                int row = s >> 4, c = s & 15;
                *reinterpret_cast<uint4*>(sm5 + SM_A + row * L5_STRIDE + c * 16) = ap[s];
            }
        }
        __syncthreads();

        float acc[2][4][4];
#pragma unroll
        for (int mi = 0; mi < 2; ++mi)
#pragma unroll
            for (int nf = 0; nf < 4; ++nf)
#pragma unroll
                for (int j = 0; j < 4; ++j) acc[mi][nf][j] = 0.0f;

#pragma unroll
        for (int ks = 0; ks < 8; ++ks) {
            uint32_t a[2][4], b[2][4];
#pragma unroll
            for (int mi = 0; mi < 2; ++mi)
                ldm4(a[mi], aBase + mi * 16 * L5_STRIDE + ks * 32);
#pragma unroll
            for (int nj = 0; nj < 2; ++nj)
                ldm4(b[nj], bBase + nj * 16 * L5_STRIDE + ks * 32);
#pragma unroll
            for (int mi = 0; mi < 2; ++mi)
#pragma unroll
                for (int nf = 0; nf < 4; ++nf)
                    mma_f16(acc[mi][nf], a[mi],
                            b[nf >> 1][(nf & 1) * 2], b[nf >> 1][(nf & 1) * 2 + 1]);
        }

        // stage 64x128 tile (+bias); accumulate stats
#pragma unroll
        for (int mi = 0; mi < 2; ++mi) {
            int rl = m0 + mi * 16 + (lane >> 2);
#pragma unroll
            for (int nf = 0; nf < 4; ++nf) {
                int cl = n0 + nf * 8 + (lane & 3) * 2;
                float b0 = sbias[cl], b1 = sbias[cl + 1];
                float c0 = acc[mi][nf][0] + b0, c1 = acc[mi][nf][1] + b1;
                float c2 = acc[mi][nf][2] + b0, c3 = acc[mi][nf][3] + b1;
                stag[rl * 132 + cl] = c0;       stag[rl * 132 + cl + 1] = c1;
                stag[(rl + 8) * 132 + cl] = c2; stag[(rl + 8) * 132 + cl + 1] = c3;
                s1[nf][0] += c0 + c2;           s1[nf][1] += c1 + c3;
                s2[nf][0] += c0 * c0 + c2 * c2; s2[nf][1] += c1 * c1 + c3 * c3;
            }
        }
        __syncthreads();

        // per-molecule max/min scan -> head/tail buffers (no atomics; molecule id GLOBAL)
        int bStart = rowCta / PLEN, bEnd = (rowCta + 63) / PLEN;
        int nm = bEnd - bStart + 1;
        for (int tk = tid; tk < nm * 128; tk += 256) {
            int bi = tk >> 7, c = tk & 127;
            int b = bStart + bi;
            int r0 = b * PLEN - rowCta, r1 = r0 + PLEN;
            int a0 = r0 > 0 ? r0 : 0, a1 = r1 < 64 ? r1 : 64;
            float mx = -FLT_MAX, mn = FLT_MAX;
            for (int r = a0; r < a1; ++r) {
                float v = stag[r * 132 + c];
                mx = fmaxf(mx, v); mn = fminf(mn, v);
            }
            size_t gi = (size_t)b * 1024 + colBase + c;
            if (r0 >= 0) { g_mxH[gi] = mx; g_mnH[gi] = mn; }
            else         { g_mxT[gi] = mx; g_mnT[gi] = mn; }
        }
    }

    // stats atomics once per CTA
#pragma unroll
    for (int nf = 0; nf < 4; ++nf)
#pragma unroll
        for (int j = 0; j < 2; ++j) {
            float v1 = s1[nf][j], v2 = s2[nf][j];
            v1 += __shfl_xor_sync(0xffffffffu, v1, 4);
            v1 += __shfl_xor_sync(0xffffffffu, v1, 8);
            v1 += __shfl_xor_sync(0xffffffffu, v1, 16);
            v2 += __shfl_xor_sync(0xffffffffu, v2, 4);
            v2 += __shfl_xor_sync(0xffffffffu, v2, 8);
            v2 += __shfl_xor_sync(0xffffffffu, v2, 16);
            if (lane < 4) {
                int col = colBase + n0 + nf * 8 + lane * 2 + j;
                atomicAdd(&g_sum[tw][4][col], v1);
                atomicAdd(&g_sq [tw][4][col], v2);
            }
        }
}

// ---------------- max-pool + inline BN affine + embedding: 4 molecules/block ----------------
__global__ void __launch_bounds__(256)
maxpool_embed_kernel(const float* __restrict__ embW, const float* __restrict__ embB,
                     const float* __restrict__ gamma, const float* __restrict__ beta,
                     float* __restrict__ out) {
    int bg0 = blockIdx.x * 4;             // 4 molecules, same tower (4096 % 4 == 0)
    int tw = bg0 >> 12;
    int tid = threadIdx.x;
    __shared__ float sAa[1024], sAd[1024];
    __shared__ float sE[4][10];
    const float invN = 1.0f / (float)N_NODES;
    for (int cc = tid; cc < 1024; cc += 256) {
        float mu  = g_sum[tw][4][cc] * invN;
        float var = g_sq[tw][4][cc] * invN - mu * mu;
        float a = gamma[cc] * rsqrtf(var + BN_EPS);
        sAa[cc] = a;
        sAd[cc] = beta[cc] - mu * a;
    }
    if (tid < 40) sE[tid / 10][tid % 10] = 0.0f;
    __syncthreads();

    float acc[4][10];
#pragma unroll
    for (int m = 0; m < 4; ++m)
#pragma unroll
        for (int j = 0; j < 10; ++j) acc[m][j] = 0.0f;

    for (int cc = tid; cc < 1024; cc += 256) {
        float a = sAa[cc], d = sAd[cc];
        float w[10];
#pragma unroll
        for (int j = 0; j < 10; ++j) w[j] = embW[cc * 10 + j];
#pragma unroll
        for (int m = 0; m < 4; ++m) {
            int bg = bg0 + m;
            int sCta = (bg * PLEN) / 64, eCta = (bg * PLEN + PLEN - 1) / 64;
            size_t gi = (size_t)bg * 1024 + cc;
            float mx = g_mxH[gi], mn = g_mnH[gi];
            if (sCta != eCta) {
                mx = fmaxf(mx, g_mxT[gi]);
                mn = fminf(mn, g_mnT[gi]);
            }
            float pooled = fmaxf(fmaxf(fmaf(a, mx, d), fmaf(a, mn, d)), 0.0f);
#pragma unroll
            for (int j = 0; j < 10; ++j)
                acc[m][j] = fmaf(pooled, w[j], acc[m][j]);
        }
    }
#pragma unroll
    for (int m = 0; m < 4; ++m)
#pragma unroll
        for (int j = 0; j < 10; ++j) {
            float v = acc[m][j];
            for (int off = 16; off; off >>= 1) v += __shfl_down_sync(0xffffffffu, v, off);
            if ((tid & 31) == 0) atomicAdd(&sE[m][j], v);
        }
    __syncthreads();
    if (tid < 40) {
        int m = tid / 10, j = tid % 10;
        int bl = (bg0 + m) & (BATCH - 1);
        float e = sE[m][j] + embB[j];
        out[(tw ? O_E2 : O_E1) + bl * 10 + j] = e;
        g_e[tw][bl * 10 + j] = e;
    }
}

// ---------------- cluster assignment (8 molecules per block, both towers) ----------------
__global__ void __launch_bounds__(256)
cluster_kernel(const float* __restrict__ clu, float* __restrict__ out) {
    int tid = threadIdx.x;
    __shared__ float sclu[8000];
    __shared__ float se[10];
    __shared__ float squn[800];
    __shared__ float sred[9];
    for (int s = tid; s < 8000; s += 256) sclu[s] = clu[s];
    for (int bb = 0; bb < 8; ++bb) {
        int bg = blockIdx.x * 8 + bb;
        int tw = bg >> 12, bl = bg & (BATCH - 1);
        float* qo = out + (tw ? O_C2 : O_C1) + (size_t)bl * 800;
        float* dq = (tw == 0) ? out + O_D1 + (size_t)bl * 800 : (float*)0;
        __syncthreads();
        if (tid < 10) se[tid] = g_e[tw][bl * 10 + tid];
        __syncthreads();
        float local = 0.0f;
        for (int j = tid; j < 800; j += 256) {
            float dist = 0.0f;
#pragma unroll
            for (int k = 0; k < 10; ++k) {
                float t = se[k] - sclu[j * 10 + k];
                dist = fmaf(t, t, dist);
            }
            float qun = 1.0f / (1.0f + dist);
            squn[j] = qun; local += qun;
            if (dq) dq[j] = dist;
        }
        float v = local;
        for (int off = 16; off; off >>= 1) v += __shfl_down_sync(0xffffffffu, v, off);
        if ((tid & 31) == 0) sred[tid >> 5] = v;
        __syncthreads();
        if (tid == 0) {
            float t = 0.f;
            for (int w = 0; w < 8; ++w) t += sred[w];
            sred[8] = 1.0f / t;
        }
        __syncthreads();
        float inv = sred[8];
        for (int j = tid; j < 800; j += 256)
            qo[j] = squn[j] * inv;
    }
}

// ---------------- pairwise distance ----------------
__global__ void sim_kernel(float* __restrict__ simOut) {
    int i = blockIdx.x * blockDim.x + threadIdx.x;
    if (i >= BATCH) return;
    float s = 0.0f;
#pragma unroll
    for (int k = 0; k < 10; ++k) {
        float t = g_e[0][i * 10 + k] - g_e[1][i * 10 + k] + 1e-6f;
        s = fmaf(t, t, s);
    }
    simOut[i] = sqrtf(s);
}

// ---------------- launch ----------------
extern "C" void kernel_launch(void* const* d_in, const int* in_sizes, int n_in,
                              void* d_out, int out_size) {
    const float* x1 = (const float*)d_in[0];
    const float* x2 = (const float*)d_in[1];
    const float* W[5]; const float* bb[5]; const float* gam[5]; const float* bet[5];
    for (int li = 0; li < 5; ++li) {
        W[li]   = (const float*)d_in[2 + li * 4 + 0];
        bb[li]  = (const float*)d_in[2 + li * 4 + 1];
        gam[li] = (const float*)d_in[2 + li * 4 + 2];
        bet[li] = (const float*)d_in[2 + li * 4 + 3];
    }
    const float* embW = (const float*)d_in[22];
    const float* embB = (const float*)d_in[23];
    const float* clu  = (const float*)d_in[24];
    float* out = (float*)d_out;

    const int SMEM64  = (64 * 132 + 64 * 64  + 2 * 64) * 4;  // 50688
    const int SMEM128 = (64 * 132 + 64 * 128 + 2 * 64) * 4;  // 67072
    cudaFuncSetAttribute((const void*)gcn_gemm<64, 64>,
                         cudaFuncAttributeMaxDynamicSharedMemorySize, SMEM64);
    cudaFuncSetAttribute((const void*)gcn_gemm<64, 128>,
                         cudaFuncAttributeMaxDynamicSharedMemorySize, SMEM128);
    cudaFuncSetAttribute((const void*)layer5_mma,
                         cudaFuncAttributeMaxDynamicSharedMemorySize, SM_TOT);

    const int RT2 = TW2 / 128;   // 896 row tiles of 128

    setup_kernel<<<512, 256>>>(W[4]);
    layer1_kernel<<<TW2 / 64, 256>>>(x1, x2, W[0], bb[0]);
    gcn_gemm<64, 64><<<dim3(RT2, 1), 256, SMEM64>>>(W[1], bb[1], 0, 1,
                                                    gam[0], bet[0], 0, 1, 64);
    gcn_gemm<64, 64><<<dim3(RT2, 1), 256, SMEM64>>>(W[2], bb[2], 1, 0,
                                                    gam[1], bet[1], 1, 2, 64);
    gcn_gemm<64, 128><<<dim3(RT2, 1), 256, SMEM128>>>(W[3], bb[3], 0, 1,
                                                      gam[2], bet[2], 2, 3, 128);
    prep_A5_kernel<<<RT2, 256>>>(gam[3], bet[3]);
    layer5_mma<<<dim3(8, TW2 / 512), 256, SM_TOT>>>(bb[4]);
    maxpool_embed_kernel<<<2 * BATCH / 4, 256>>>(embW, embB, gam[4], bet[4], out);
    cluster_kernel<<<2 * BATCH / 8, 256>>>(clu, out);
    sim_kernel<<<16, 256>>>(out);
}

// round 17
// speedup vs baseline: 1.0619x; 1.0619x over previous
#include <cuda_runtime.h>
#include <cuda_fp16.h>
#include <math.h>
#include <stdint.h>
#include <float.h>

#define PLEN 14
#define BATCH 4096
#define N_NODES (BATCH * PLEN)   // 57344
#define TW2 (2 * N_NODES)        // both towers
#define BN_EPS 1e-5f

// Output layout: concat of (sim[B], c1[B,800], c2[B,800], e1[B,10], e2[B,10], d1[B,800])
#define O_SIM 0
#define O_C1  4096
#define O_C2  (4096 + 3276800)
#define O_E1  (4096 + 2*3276800)
#define O_E2  (O_E1 + 40960)
#define O_D1  (O_E2 + 40960)

// ---------------- scratch (device globals; no allocation) ----------------
__device__ float g_hA[(size_t)TW2 * 128];
__device__ float g_hB[(size_t)TW2 * 128];
__device__ float g_sum[2][5][1024];
__device__ float g_sq [2][5][1024];
__device__ float g_e  [2][BATCH * 10];
__device__ __align__(16) __half g_A5[(size_t)TW2 * 128];     // fp16 A (layer4 + layer5)
__device__ __align__(16) __half g_W5T[1024 * 128];           // W5^T fp16: [n][k]
__device__ __align__(16) __half g_W4T[128 * 128];            // W4^T fp16 padded: [128n][128k]
// per-(molecule,col) pooling partials; molecule id is GLOBAL (0..2*BATCH-1)
__device__ float g_mxH[2 * BATCH * 1024], g_mnH[2 * BATCH * 1024];
__device__ float g_mxT[2 * BATCH * 1024], g_mnT[2 * BATCH * 1024];

// ---------------- setup: W5 transpose->fp16 + zero BN stat accumulators ----------------
__global__ void setup_kernel(const float* __restrict__ W5) {
    int i = blockIdx.x * 256 + threadIdx.x;   // 0..131071
    if (i < 2 * 5 * 1024) {
        (&g_sum[0][0][0])[i] = 0.0f;
        (&g_sq [0][0][0])[i] = 0.0f;
    }
    int k = i >> 10, n = i & 1023;            // 128*1024 total
    g_W5T[n * 128 + k] = __float2half(W5[i]);
}

// ---------------- W4 [64][128] fp32 -> padded transposed fp16 [128n][128k] ----------------
__global__ void prep_W4_kernel(const float* __restrict__ W4) {
    int i = blockIdx.x * 256 + threadIdx.x;   // 128*128
    int n = i >> 7, k = i & 127;
    float v = (k < 64) ? W4[k * 128 + n] : 0.0f;
    g_W4T[n * 128 + k] = __float2half(v);
}

// ---------------- layer 1 (both towers), stride-64 output ----------------
__global__ void __launch_bounds__(256) layer1_kernel(const float* __restrict__ x1,
                                                     const float* __restrict__ x2,
                                                     const float* __restrict__ W1,
                                                     const float* __restrict__ b1) {
    __shared__ float xg[64][3];
    int tid = threadIdx.x;
    int rowBase = blockIdx.x * 64;
    int tw = rowBase >= N_NODES;
    const float* x = tw ? x2 : x1;
    int locBase = rowBase - tw * N_NODES;
    if (tid < 192) {
        int i = tid / 3, k = tid % 3;
        int nl = locBase + i, b = nl / PLEN, p = nl % PLEN;
        const float* xb = x + (size_t)b * 3 * PLEN + k * PLEN;
        float v = 0.0f;
        if (p > 0)        v += xb[p - 1];
        if (p < PLEN - 1) v += xb[p + 1];
        xg[i][k] = v;
    }
    __syncthreads();
    int c = tid & 63, rg = tid >> 6;
    float w0 = W1[c], w1 = W1[64 + c], w2 = W1[128 + c], bb = b1[c];
    float s1 = 0.0f, s2 = 0.0f;
    for (int ii = 0; ii < 16; ++ii) {
        int i = rg * 16 + ii;
        float v = fmaf(xg[i][0], w0, fmaf(xg[i][1], w1, fmaf(xg[i][2], w2, bb)));
        g_hA[(size_t)(rowBase + i) * 64 + c] = v;
        s1 += v; s2 = fmaf(v, v, s2);
    }
    atomicAdd(&g_sum[tw][0][c], s1);
    atomicAdd(&g_sq [tw][0][c], s2);
}

// ---------------- fp32 GCN GEMM (layers 2-3), M=128 tile, in-block BN affine ----------------
template<int K, int NT>
__global__ void __launch_bounds__(256)
gcn_gemm(const float* __restrict__ W, const float* __restrict__ bias,
         int srcBuf, int dstBuf,
         const float* __restrict__ gammaP, const float* __restrict__ betaP,
         int statPrev, int statIdx, int DOUT) {
    constexpr int M = 128, TN = NT / 16, K4 = K / 4, NT4 = NT / 4, MP = M + 4;
    extern __shared__ float sm[];
    float* As = sm;
    float* Bs = As + K * MP;
    float* sA = Bs + K * NT;
    float* sD = sA + K;

    const float* prev = srcBuf ? g_hB : g_hA;
    float* out = dstBuf ? g_hB : g_hA;

    int tid = threadIdx.x, tx = tid & 15, ty = tid >> 4;
    int rowBase = blockIdx.x * M, colBase = blockIdx.y * NT;
    int tw = rowBase >= N_NODES;

    if (tid < K) {
        const float invN = 1.0f / (float)N_NODES;
        float mu  = g_sum[tw][statPrev][tid] * invN;
        float var = g_sq[tw][statPrev][tid] * invN - mu * mu;
        float s = gammaP[tid] * rsqrtf(var + BN_EPS);
        sA[tid] = s; sD[tid] = betaP[tid] - mu * s;
    }
    for (int s = tid; s < K * NT4; s += 256) {
        int k = s / NT4, j = (s - k * NT4) * 4;
        float4 w = *reinterpret_cast<const float4*>(W + (size_t)k * DOUT + colBase + j);
        *reinterpret_cast<float4*>(&Bs[k * NT + j]) = w;
    }
    __syncthreads();
    for (int s = tid; s < M * K4; s += 256) {
        int i = s / K4, kq = (s - i * K4) * 4;
        int n = rowBase + i, p = n % PLEN;
        float v0 = 0.f, v1 = 0.f, v2 = 0.f, v3 = 0.f;
        float a0 = sA[kq], a1 = sA[kq + 1], a2 = sA[kq + 2], a3 = sA[kq + 3];
        float d0 = sD[kq], d1 = sD[kq + 1], d2 = sD[kq + 2], d3 = sD[kq + 3];
        if (p > 0) {
            float4 L = *reinterpret_cast<const float4*>(prev + (size_t)(n - 1) * K + kq);
            v0 += fmaxf(fmaf(a0, L.x, d0), 0.f);
            v1 += fmaxf(fmaf(a1, L.y, d1), 0.f);
            v2 += fmaxf(fmaf(a2, L.z, d2), 0.f);
            v3 += fmaxf(fmaf(a3, L.w, d3), 0.f);
        }
        if (p < PLEN - 1) {
            float4 R = *reinterpret_cast<const float4*>(prev + (size_t)(n + 1) * K + kq);
            v0 += fmaxf(fmaf(a0, R.x, d0), 0.f);
            v1 += fmaxf(fmaf(a1, R.y, d1), 0.f);
            v2 += fmaxf(fmaf(a2, R.z, d2), 0.f);
            v3 += fmaxf(fmaf(a3, R.w, d3), 0.f);
        }
        As[(kq + 0) * MP + i] = v0;
        As[(kq + 1) * MP + i] = v1;
        As[(kq + 2) * MP + i] = v2;
        As[(kq + 3) * MP + i] = v3;
    }
    __syncthreads();

    float acc[8][TN];
#pragma unroll
    for (int r = 0; r < 8; ++r)
#pragma unroll
        for (int j = 0; j < TN; ++j) acc[r][j] = 0.0f;

    int r0 = ty * 8, c0 = tx * TN;
#pragma unroll 4
    for (int k = 0; k < K; ++k) {
        float4 a4a = *reinterpret_cast<const float4*>(&As[k * MP + r0]);
        float4 a4b = *reinterpret_cast<const float4*>(&As[k * MP + r0 + 4]);
        float ar[8] = {a4a.x, a4a.y, a4a.z, a4a.w, a4b.x, a4b.y, a4b.z, a4b.w};
        float br[TN];
#pragma unroll
        for (int j = 0; j < TN; j += 4) {
            float4 b4 = *reinterpret_cast<const float4*>(&Bs[k * NT + c0 + j]);
            br[j] = b4.x; br[j + 1] = b4.y; br[j + 2] = b4.z; br[j + 3] = b4.w;
        }
#pragma unroll
        for (int r = 0; r < 8; ++r)
#pragma unroll
            for (int j = 0; j < TN; ++j)
                acc[r][j] = fmaf(ar[r], br[j], acc[r][j]);
    }
    __syncthreads();

    float bl[TN];
#pragma unroll
    for (int j = 0; j < TN; ++j) bl[j] = bias[colBase + c0 + j];

    float s1[TN], s2[TN];
#pragma unroll
    for (int j = 0; j < TN; ++j) { s1[j] = 0.f; s2[j] = 0.f; }

#pragma unroll
    for (int r = 0; r < 8; ++r) {
        float vrow[TN];
#pragma unroll
        for (int j = 0; j < TN; ++j) {
            float v = acc[r][j] + bl[j];
            vrow[j] = v; s1[j] += v; s2[j] = fmaf(v, v, s2[j]);
        }
        float* op = out + (size_t)(rowBase + r0 + r) * DOUT + colBase + c0;
#pragma unroll
        for (int j = 0; j < TN; j += 4) {
            float4 o = make_float4(vrow[j], vrow[j + 1], vrow[j + 2], vrow[j + 3]);
            *reinterpret_cast<float4*>(op + j) = o;
        }
    }
    float* red = As;
#pragma unroll
    for (int j = 0; j < TN; ++j) {
        red[ty * NT + c0 + j] = s1[j];
        red[16 * NT + ty * NT + c0 + j] = s2[j];
    }
    __syncthreads();
    if (tid < NT) {
        float t1 = 0.f, t2 = 0.f;
        for (int y = 0; y < 16; ++y) {
            t1 += red[y * NT + tid];
            t2 += red[16 * NT + y * NT + tid];
        }
        atomicAdd(&g_sum[tw][statIdx][colBase + tid], t1);
        atomicAdd(&g_sq [tw][statIdx][colBase + tid], t2);
    }
}

// ---------------- A prep for layer4: agg(relu(BN2(g_hA, stride 64))) -> padded fp16 ----------------
__global__ void __launch_bounds__(256) prep_A4_kernel(const float* __restrict__ gamma,
                                                      const float* __restrict__ beta) {
    __shared__ float sa[64], sd[64];
    int tid = threadIdx.x;
    int rowCta = blockIdx.x * 128;
    int tw = rowCta >= N_NODES;
    if (tid < 64) {
        const float invN = 1.0f / (float)N_NODES;
        float mu  = g_sum[tw][2][tid] * invN;
        float var = g_sq[tw][2][tid] * invN - mu * mu;
        float s = gamma[tid] * rsqrtf(var + BN_EPS);
        sa[tid] = s; sd[tid] = beta[tid] - mu * s;
    }
    __syncthreads();
    for (int u = tid; u < 128 * 32; u += 256) {
        int i = u >> 5, kq = (u & 31) * 4;
        int n = rowCta + i;
        float v0 = 0.f, v1 = 0.f, v2 = 0.f, v3 = 0.f;
        if (kq < 64) {
            int p = n % PLEN;
            float4 a = *reinterpret_cast<const float4*>(sa + kq);
            float4 d = *reinterpret_cast<const float4*>(sd + kq);
            if (p > 0) {
                float4 L = *reinterpret_cast<const float4*>(g_hA + (size_t)(n - 1) * 64 + kq);
                v0 += fmaxf(fmaf(a.x, L.x, d.x), 0.f);
                v1 += fmaxf(fmaf(a.y, L.y, d.y), 0.f);
                v2 += fmaxf(fmaf(a.z, L.z, d.z), 0.f);
                v3 += fmaxf(fmaf(a.w, L.w, d.w), 0.f);
            }
            if (p < PLEN - 1) {
                float4 R = *reinterpret_cast<const float4*>(g_hA + (size_t)(n + 1) * 64 + kq);
                v0 += fmaxf(fmaf(a.x, R.x, d.x), 0.f);
                v1 += fmaxf(fmaf(a.y, R.y, d.y), 0.f);
                v2 += fmaxf(fmaf(a.z, R.z, d.z), 0.f);
                v3 += fmaxf(fmaf(a.w, R.w, d.w), 0.f);
            }
        }
        size_t o = (size_t)n * 128 + kq;
        __half2* ph = reinterpret_cast<__half2*>(g_A5 + o);
        ph[0] = __halves2half2(__float2half(v0), __float2half(v1));
        ph[1] = __halves2half2(__float2half(v2), __float2half(v3));
    }
}

// ================= fp16 mma kernels =================
// smem layout (byte offsets); rows padded to 272B for conflict-free ldmatrix
// A: 64 rows fp16, B: 128 rows fp16, staging [64][132] fp32, bias. 2 CTAs/SM.
#define L5_STRIDE 272
#define SM_A    0
#define SM_BH   17408
#define SM_STAG 52224
#define SM_BIAS 86016
#define SM_TOT  86528

__device__ __forceinline__ uint32_t smem_u32(const void* p) {
    uint32_t a;
    asm("{ .reg .u64 t; cvta.to.shared.u64 t, %1; cvt.u32.u64 %0, t; }" : "=r"(a) : "l"(p));
    return a;
}
__device__ __forceinline__ void ldm4(uint32_t* r, uint32_t addr) {
    asm volatile("ldmatrix.sync.aligned.m8n8.x4.shared.b16 {%0,%1,%2,%3}, [%4];"
                 : "=r"(r[0]), "=r"(r[1]), "=r"(r[2]), "=r"(r[3]) : "r"(addr));
}
__device__ __forceinline__ void mma_f16(float* c, const uint32_t* a,
                                        uint32_t b0, uint32_t b1) {
    asm volatile(
        "mma.sync.aligned.m16n8k16.row.col.f32.f16.f16.f32 "
        "{%0,%1,%2,%3}, {%4,%5,%6,%7}, {%8,%9}, {%0,%1,%2,%3};"
        : "+f"(c[0]), "+f"(c[1]), "+f"(c[2]), "+f"(c[3])
        : "r"(a[0]), "r"(a[1]), "r"(a[2]), "r"(a[3]), "r"(b0), "r"(b1));
}

// ---------------- layer4: clone of layer5_mma; colBase=0, B=g_W4T, direct copy-out ----------------
__global__ void __launch_bounds__(256, 2)
layer4_mma(const float* __restrict__ bias) {
    extern __shared__ char sm4[];
    int tid = threadIdx.x, wid = tid >> 5, lane = tid & 31;
    int rowCta0 = blockIdx.x * 512;
    int tw = rowCta0 >= N_NODES;
    float* sbias = reinterpret_cast<float*>(sm4 + SM_BIAS);
    if (tid < 128) sbias[tid] = bias[tid];

    // B tile: 128 n-rows x 128 k fp16 (padded W4^T)
    {
        const uint4* bp = reinterpret_cast<const uint4*>(g_W4T);
#pragma unroll
        for (int t = 0; t < 8; ++t) {
            int s = tid + t * 256;
            int row = s >> 4, c = s & 15;
            *reinterpret_cast<uint4*>(sm4 + SM_BH + row * L5_STRIDE + c * 16) = bp[s];
        }
    }

    int wm = wid >> 2, wn = wid & 3;
    int m0 = wm * 32, n0 = wn * 32;
    int quad = lane >> 3, r8 = lane & 7;
    uint32_t base = smem_u32(sm4);
    uint32_t aBase = base + SM_A + (uint32_t)((m0 + (quad & 1) * 8 + r8) * L5_STRIDE + (quad >> 1) * 16);
    uint32_t bBase = base + SM_BH + (uint32_t)((n0 + (quad >> 1) * 8 + r8) * L5_STRIDE + (quad & 1) * 16);

    float s1[4][2], s2[4][2];
#pragma unroll
    for (int nf = 0; nf < 4; ++nf) { s1[nf][0] = s1[nf][1] = 0.f; s2[nf][0] = s2[nf][1] = 0.f; }

    float* stag = reinterpret_cast<float*>(sm4 + SM_STAG);   // [64][132]

#pragma unroll 1
    for (int it = 0; it < 8; ++it) {
        int rowCta = rowCta0 + it * 64;
        __syncthreads();   // prev iter fully done before A/staging overwrite
        {
            const uint4* ap = reinterpret_cast<const uint4*>(g_A5) + (size_t)rowCta * 16;
#pragma unroll
            for (int t = 0; t < 4; ++t) {
                int s = tid + t * 256;
                int row = s >> 4, c = s & 15;
                *reinterpret_cast<uint4*>(sm4 + SM_A + row * L5_STRIDE + c * 16) = ap[s];
            }
        }
        __syncthreads();

        float acc[2][4][4];
#pragma unroll
        for (int mi = 0; mi < 2; ++mi)
#pragma unroll
            for (int nf = 0; nf < 4; ++nf)
#pragma unroll
                for (int j = 0; j < 4; ++j) acc[mi][nf][j] = 0.0f;

#pragma unroll
        for (int ks = 0; ks < 8; ++ks) {
            uint32_t a[2][4], b[2][4];
#pragma unroll
            for (int mi = 0; mi < 2; ++mi)
                ldm4(a[mi], aBase + mi * 16 * L5_STRIDE + ks * 32);
#pragma unroll
            for (int nj = 0; nj < 2; ++nj)
                ldm4(b[nj], bBase + nj * 16 * L5_STRIDE + ks * 32);
#pragma unroll
            for (int mi = 0; mi < 2; ++mi)
#pragma unroll
                for (int nf = 0; nf < 4; ++nf)
                    mma_f16(acc[mi][nf], a[mi],
                            b[nf >> 1][(nf & 1) * 2], b[nf >> 1][(nf & 1) * 2 + 1]);
        }

        // stage 64x128 tile (+bias); accumulate stats (identical mapping to layer5)
#pragma unroll
        for (int mi = 0; mi < 2; ++mi) {
            int rl = m0 + mi * 16 + (lane >> 2);
#pragma unroll
            for (int nf = 0; nf < 4; ++nf) {
                int cl = n0 + nf * 8 + (lane & 3) * 2;
                float b0 = sbias[cl], b1 = sbias[cl + 1];
                float c0 = acc[mi][nf][0] + b0, c1 = acc[mi][nf][1] + b1;
                float c2 = acc[mi][nf][2] + b0, c3 = acc[mi][nf][3] + b1;
                stag[rl * 132 + cl] = c0;       stag[rl * 132 + cl + 1] = c1;
                stag[(rl + 8) * 132 + cl] = c2; stag[(rl + 8) * 132 + cl + 1] = c3;
                s1[nf][0] += c0 + c2;           s1[nf][1] += c1 + c3;
                s2[nf][0] += c0 * c0 + c2 * c2; s2[nf][1] += c1 * c1 + c3 * c3;
            }
        }
        __syncthreads();

        // copy-out: stag -> g_hB rows (stride 128), coalesced
        for (int s = tid; s < 64 * 128; s += 256) {
            int r = s >> 7, c = s & 127;
            g_hB[(size_t)(rowCta + r) * 128 + c] = stag[r * 132 + c];
        }
    }

    // stats atomics once per CTA -> layer-4 stats (index 3)
#pragma unroll
    for (int nf = 0; nf < 4; ++nf)
#pragma unroll
        for (int j = 0; j < 2; ++j) {
            float v1 = s1[nf][j], v2 = s2[nf][j];
            v1 += __shfl_xor_sync(0xffffffffu, v1, 4);
            v1 += __shfl_xor_sync(0xffffffffu, v1, 8);
            v1 += __shfl_xor_sync(0xffffffffu, v1, 16);
            v2 += __shfl_xor_sync(0xffffffffu, v2, 4);
            v2 += __shfl_xor_sync(0xffffffffu, v2, 8);
            v2 += __shfl_xor_sync(0xffffffffu, v2, 16);
            if (lane < 4) {
                int col = n0 + nf * 8 + lane * 2 + j;
                atomicAdd(&g_sum[tw][3][col], v1);
                atomicAdd(&g_sq [tw][3][col], v2);
            }
        }
}

// ---------------- A prep for layer5 (unchanged, reads g_hB stride 128) ----------------
__global__ void __launch_bounds__(256) prep_A5_kernel(const float* __restrict__ gamma,
                                                      const float* __restrict__ beta) {
    __shared__ float sa[128], sd[128];
    int tid = threadIdx.x;
    int rowCta = blockIdx.x * 128;
    int tw = rowCta >= N_NODES;
    if (tid < 128) {
        const float invN = 1.0f / (float)N_NODES;
        float mu  = g_sum[tw][3][tid] * invN;
        float var = g_sq[tw][3][tid] * invN - mu * mu;
        float s = gamma[tid] * rsqrtf(var + BN_EPS);
        sa[tid] = s; sd[tid] = beta[tid] - mu * s;
    }
    __syncthreads();
    for (int u = tid; u < 128 * 32; u += 256) {
        int i = u >> 5, kq = (u & 31) * 4;
        int n = rowCta + i, p = n % PLEN;
        float4 a = *reinterpret_cast<const float4*>(sa + kq);
        float4 d = *reinterpret_cast<const float4*>(sd + kq);
        float v0 = 0.f, v1 = 0.f, v2 = 0.f, v3 = 0.f;
        if (p > 0) {
            float4 L = *reinterpret_cast<const float4*>(g_hB + (size_t)(n - 1) * 128 + kq);
            v0 += fmaxf(fmaf(a.x, L.x, d.x), 0.f);
            v1 += fmaxf(fmaf(a.y, L.y, d.y), 0.f);
            v2 += fmaxf(fmaf(a.z, L.z, d.z), 0.f);
            v3 += fmaxf(fmaf(a.w, L.w, d.w), 0.f);
        }
        if (p < PLEN - 1) {
            float4 R = *reinterpret_cast<const float4*>(g_hB + (size_t)(n + 1) * 128 + kq);
            v0 += fmaxf(fmaf(a.x, R.x, d.x), 0.f);
            v1 += fmaxf(fmaf(a.y, R.y, d.y), 0.f);
            v2 += fmaxf(fmaf(a.z, R.z, d.z), 0.f);
            v3 += fmaxf(fmaf(a.w, R.w, d.w), 0.f);
        }
        size_t o = (size_t)n * 128 + kq;
        __half2* ph = reinterpret_cast<__half2*>(g_A5 + o);
        ph[0] = __halves2half2(__float2half(v0), __float2half(v1));
        ph[1] = __halves2half2(__float2half(v2), __float2half(v3));
    }
}

// ---------------- layer5 (unchanged from R13) ----------------
__global__ void __launch_bounds__(256, 2)
layer5_mma(const float* __restrict__ bias) {
    extern __shared__ char sm5[];
    int tid = threadIdx.x, wid = tid >> 5, lane = tid & 31;
    int colBase = blockIdx.x * 128;
    int rowCta0 = blockIdx.y * 512;
    int tw = rowCta0 >= N_NODES;
    float* sbias = reinterpret_cast<float*>(sm5 + SM_BIAS);
    if (tid < 128) sbias[tid] = bias[colBase + tid];

    {
        const uint4* bp = reinterpret_cast<const uint4*>(g_W5T) + (size_t)colBase * 16;
#pragma unroll
        for (int t = 0; t < 8; ++t) {
            int s = tid + t * 256;
            int row = s >> 4, c = s & 15;
            *reinterpret_cast<uint4*>(sm5 + SM_BH + row * L5_STRIDE + c * 16) = bp[s];
        }
    }

    int wm = wid >> 2, wn = wid & 3;
    int m0 = wm * 32, n0 = wn * 32;
    int quad = lane >> 3, r8 = lane & 7;
    uint32_t base = smem_u32(sm5);
    uint32_t aBase = base + SM_A + (uint32_t)((m0 + (quad & 1) * 8 + r8) * L5_STRIDE + (quad >> 1) * 16);
    uint32_t bBase = base + SM_BH + (uint32_t)((n0 + (quad >> 1) * 8 + r8) * L5_STRIDE + (quad & 1) * 16);

    float s1[4][2], s2[4][2];
#pragma unroll
    for (int nf = 0; nf < 4; ++nf) { s1[nf][0] = s1[nf][1] = 0.f; s2[nf][0] = s2[nf][1] = 0.f; }

    float* stag = reinterpret_cast<float*>(sm5 + SM_STAG);   // [64][132]

#pragma unroll 1
    for (int it = 0; it < 8; ++it) {
        int rowCta = rowCta0 + it * 64;
        __syncthreads();
        {
            const uint4* ap = reinterpret_cast<const uint4*>(g_A5) + (size_t)rowCta * 16;
#pragma unroll
            for (int t = 0; t < 4; ++t) {
                int s = tid + t * 256;
                int row = s >> 4, c = s & 15;
                *reinterpret_cast<uint4*>(sm5 + SM_A + row * L5_STRIDE + c * 16) = ap[s];
            }
        }
        __syncthreads();

        float acc[2][4][4];
#pragma unroll
        for (int mi = 0; mi < 2; ++mi)
#pragma unroll
            for (int nf = 0; nf < 4; ++nf)
#pragma unroll
                for (int j = 0; j < 4; ++j) acc[mi][nf][j] = 0.0f;

#pragma unroll
        for (int ks = 0; ks < 8; ++ks) {
            uint32_t a[2][4], b[2][4];
#pragma unroll
            for (int mi = 0; mi < 2; ++mi)
                ldm4(a[mi], aBase + mi * 16 * L5_STRIDE + ks * 32);
#pragma unroll
            for (int nj = 0; nj < 2; ++nj)
                ldm4(b[nj], bBase + nj * 16 * L5_STRIDE + ks * 32);
#pragma unroll
            for (int mi = 0; mi < 2; ++mi)
#pragma unroll
                for (int nf = 0; nf < 4; ++nf)
                    mma_f16(acc[mi][nf], a[mi],
                            b[nf >> 1][(nf & 1) * 2], b[nf >> 1][(nf & 1) * 2 + 1]);
        }

#pragma unroll
        for (int mi = 0; mi < 2; ++mi) {
            int rl = m0 + mi * 16 + (lane >> 2);
#pragma unroll
            for (int nf = 0; nf < 4; ++nf) {
                int cl = n0 + nf * 8 + (lane & 3) * 2;
                float b0 = sbias[cl], b1 = sbias[cl + 1];
                float c0 = acc[mi][nf][0] + b0, c1 = acc[mi][nf][1] + b1;
                float c2 = acc[mi][nf][2] + b0, c3 = acc[mi][nf][3] + b1;
                stag[rl * 132 + cl] = c0;       stag[rl * 132 + cl + 1] = c1;
                stag[(rl + 8) * 132 + cl] = c2; stag[(rl + 8) * 132 + cl + 1] = c3;
                s1[nf][0] += c0 + c2;           s1[nf][1] += c1 + c3;
                s2[nf][0] += c0 * c0 + c2 * c2; s2[nf][1] += c1 * c1 + c3 * c3;
            }
        }
        __syncthreads();

        int bStart = rowCta / PLEN, bEnd = (rowCta + 63) / PLEN;
        int nm = bEnd - bStart + 1;
        for (int tk = tid; tk < nm * 128; tk += 256) {
            int bi = tk >> 7, c = tk & 127;
            int b = bStart + bi;
            int r0 = b * PLEN - rowCta, r1 = r0 + PLEN;
            int a0 = r0 > 0 ? r0 : 0, a1 = r1 < 64 ? r1 : 64;
            float mx = -FLT_MAX, mn = FLT_MAX;
            for (int r = a0; r < a1; ++r) {
                float v = stag[r * 132 + c];
                mx = fmaxf(mx, v); mn = fminf(mn, v);
            }
            size_t gi = (size_t)b * 1024 + colBase + c;
            if (r0 >= 0) { g_mxH[gi] = mx; g_mnH[gi] = mn; }
            else         { g_mxT[gi] = mx; g_mnT[gi] = mn; }
        }
    }

#pragma unroll
    for (int nf = 0; nf < 4; ++nf)
#pragma unroll
        for (int j = 0; j < 2; ++j) {
            float v1 = s1[nf][j], v2 = s2[nf][j];
            v1 += __shfl_xor_sync(0xffffffffu, v1, 4);
            v1 += __shfl_xor_sync(0xffffffffu, v1, 8);
            v1 += __shfl_xor_sync(0xffffffffu, v1, 16);
            v2 += __shfl_xor_sync(0xffffffffu, v2, 4);
            v2 += __shfl_xor_sync(0xffffffffu, v2, 8);
            v2 += __shfl_xor_sync(0xffffffffu, v2, 16);
            if (lane < 4) {
                int col = colBase + n0 + nf * 8 + lane * 2 + j;
                atomicAdd(&g_sum[tw][4][col], v1);
                atomicAdd(&g_sq [tw][4][col], v2);
            }
        }
}

// ---------------- max-pool (partials) + inline BN affine + embedding (R13 config) ----------------
__global__ void __launch_bounds__(256)
maxpool_embed_kernel(const float* __restrict__ embW, const float* __restrict__ embB,
                     const float* __restrict__ gamma, const float* __restrict__ beta,
                     float* __restrict__ out) {
    int bg = blockIdx.x;
    int tw = bg >> 12, bl = bg & (BATCH - 1);
    int tid = threadIdx.x;
    int sCta = (bg * PLEN) / 64, eCta = (bg * PLEN + PLEN - 1) / 64;
    bool split = sCta != eCta;
    __shared__ float sE[10];
    if (tid < 10) sE[tid] = 0.0f;
    __syncthreads();
    float acc[10];
#pragma unroll
    for (int j = 0; j < 10; ++j) acc[j] = 0.0f;
    const float invN = 1.0f / (float)N_NODES;
    for (int cc = tid; cc < 1024; cc += 256) {
        size_t gi = (size_t)bg * 1024 + cc;
        float mx = g_mxH[gi], mn = g_mnH[gi];
        if (split) {
            mx = fmaxf(mx, g_mxT[gi]);
            mn = fminf(mn, g_mnT[gi]);
        }
        float mu  = g_sum[tw][4][cc] * invN;
        float var = g_sq[tw][4][cc] * invN - mu * mu;
        float a = gamma[cc] * rsqrtf(var + BN_EPS);
        float d = beta[cc] - mu * a;
        float pooled = fmaxf(fmaxf(fmaf(a, mx, d), fmaf(a, mn, d)), 0.0f);
#pragma unroll
        for (int j = 0; j < 10; ++j)
            acc[j] = fmaf(pooled, embW[cc * 10 + j], acc[j]);
    }
#pragma unroll
    for (int j = 0; j < 10; ++j) {
        float v = acc[j];
        for (int off = 16; off; off >>= 1) v += __shfl_down_sync(0xffffffffu, v, off);
        if ((tid & 31) == 0) atomicAdd(&sE[j], v);
    }
    __syncthreads();
    if (tid < 10) {
        float e = sE[tid] + embB[tid];
        out[(tw ? O_E2 : O_E1) + bl * 10 + tid] = e;
        g_e[tw][bl * 10 + tid] = e;
    }
}

// ---------------- cluster assignment (4 molecules per block, R13 config) ----------------
__global__ void __launch_bounds__(256)
cluster_kernel(const float* __restrict__ clu, float* __restrict__ out) {
    int tid = threadIdx.x;
    __shared__ float sclu[8000];
    __shared__ float se[10];
    __shared__ float squn[800];
    __shared__ float sred[9];
    for (int s = tid; s < 8000; s += 256) sclu[s] = clu[s];
    for (int bb = 0; bb < 4; ++bb) {
        int bg = blockIdx.x * 4 + bb;
        int tw = bg >> 12, bl = bg & (BATCH - 1);
        float* qo = out + (tw ? O_C2 : O_C1) + (size_t)bl * 800;
        float* dq = (tw == 0) ? out + O_D1 + (size_t)bl * 800 : (float*)0;
        __syncthreads();
        if (tid < 10) se[tid] = g_e[tw][bl * 10 + tid];
        __syncthreads();
        float local = 0.0f;
        for (int j = tid; j < 800; j += 256) {
            float dist = 0.0f;
#pragma unroll
            for (int k = 0; k < 10; ++k) {
                float t = se[k] - sclu[j * 10 + k];
                dist = fmaf(t, t, dist);
            }
            float qun = 1.0f / (1.0f + dist);
            squn[j] = qun; local += qun;
            if (dq) dq[j] = dist;
        }
        float v = local;
        for (int off = 16; off; off >>= 1) v += __shfl_down_sync(0xffffffffu, v, off);
        if ((tid & 31) == 0) sred[tid >> 5] = v;
        __syncthreads();
        if (tid == 0) {
            float t = 0.f;
            for (int w = 0; w < 8; ++w) t += sred[w];
            sred[8] = 1.0f / t;
        }
        __syncthreads();
        float inv = sred[8];
        for (int j = tid; j < 800; j += 256)
            qo[j] = squn[j] * inv;
    }
}

// ---------------- pairwise distance ----------------
__global__ void sim_kernel(float* __restrict__ simOut) {
    int i = blockIdx.x * blockDim.x + threadIdx.x;
    if (i >= BATCH) return;
    float s = 0.0f;
#pragma unroll
    for (int k = 0; k < 10; ++k) {
        float t = g_e[0][i * 10 + k] - g_e[1][i * 10 + k] + 1e-6f;
        s = fmaf(t, t, s);
    }
    simOut[i] = sqrtf(s);
}

// ---------------- launch ----------------
extern "C" void kernel_launch(void* const* d_in, const int* in_sizes, int n_in,
                              void* d_out, int out_size) {
    const float* x1 = (const float*)d_in[0];
    const float* x2 = (const float*)d_in[1];
    const float* W[5]; const float* bb[5]; const float* gam[5]; const float* bet[5];
    for (int li = 0; li < 5; ++li) {
        W[li]   = (const float*)d_in[2 + li * 4 + 0];
        bb[li]  = (const float*)d_in[2 + li * 4 + 1];
        gam[li] = (const float*)d_in[2 + li * 4 + 2];
        bet[li] = (const float*)d_in[2 + li * 4 + 3];
    }
    const float* embW = (const float*)d_in[22];
    const float* embB = (const float*)d_in[23];
    const float* clu  = (const float*)d_in[24];
    float* out = (float*)d_out;

    const int SMEM64 = (64 * 132 + 64 * 64 + 2 * 64) * 4;  // 50688
    cudaFuncSetAttribute((const void*)gcn_gemm<64, 64>,
                         cudaFuncAttributeMaxDynamicSharedMemorySize, SMEM64);
    cudaFuncSetAttribute((const void*)layer4_mma,
                         cudaFuncAttributeMaxDynamicSharedMemorySize, SM_TOT);
    cudaFuncSetAttribute((const void*)layer5_mma,
                         cudaFuncAttributeMaxDynamicSharedMemorySize, SM_TOT);

    const int RT2 = TW2 / 128;   // 896 row tiles of 128

    setup_kernel<<<512, 256>>>(W[4]);
    prep_W4_kernel<<<64, 256>>>(W[3]);
    layer1_kernel<<<TW2 / 64, 256>>>(x1, x2, W[0], bb[0]);
    gcn_gemm<64, 64><<<dim3(RT2, 1), 256, SMEM64>>>(W[1], bb[1], 0, 1,
                                                    gam[0], bet[0], 0, 1, 64);
    gcn_gemm<64, 64><<<dim3(RT2, 1), 256, SMEM64>>>(W[2], bb[2], 1, 0,
                                                    gam[1], bet[1], 1, 2, 64);
    prep_A4_kernel<<<RT2, 256>>>(gam[2], bet[2]);
    layer4_mma<<<TW2 / 512, 256, SM_TOT>>>(bb[3]);
    prep_A5_kernel<<<RT2, 256>>>(gam[3], bet[3]);
    layer5_mma<<<dim3(8, TW2 / 512), 256, SM_TOT>>>(bb[4]);
    maxpool_embed_kernel<<<2 * BATCH, 256>>>(embW, embB, gam[4], bet[4], out);
    cluster_kernel<<<2 * BATCH / 4, 256>>>(clu, out);
    sim_kernel<<<16, 256>>>(out);
}